// round 12
// baseline (speedup 1.0000x reference)
#include <cuda_runtime.h>

// Fixed shape: depthin (1,1,480,640) float32 -> scalar float32.
#define ROWS 480
#define COLS 640
#define TH   8
#define TW   32
#define NT   (TH * TW)    // 256
#define S    7
#define P    3
#define SMH  (TH + 2*P)   // 14
#define SMW  (TW + 2*P)   // 38
#define NBX  (COLS / TW)  // 20
#define NBY  (ROWS / TH)  // 60
#define NB   (NBX * NBY)  // 1200

__device__ float g_blocksums[NB];
__device__ unsigned int g_count = 0;

__device__ __forceinline__ float fsqrt_abs_approx(float x) {
    // |x| folds into the MUFU source operand modifier (free in SASS).
    float r;
    asm("sqrt.approx.f32 %0, %1;" : "=f"(r) : "f"(fabsf(x)));
    return r;
}

__global__ __launch_bounds__(NT, 4)
void stdev_fused_kernel(const float* __restrict__ depth, float* __restrict__ out) {
    // Separate scalar tiles: z and q = z^2 * (1 + cs^2 + rs^2) = |p|^2.
    __shared__ float szZ[SMH][SMW];
    __shared__ float szQ[SMH][SMW];
    __shared__ float wsum[NT / 32];
    __shared__ int   is_last;

    const float inv_fx = (float)(1.0 / 582.6244816773795);
    const float inv_fy = (float)(1.0 / 582.6910327098864);
    const float cx = 313.0447587080473f;
    const float cy = 238.44389626620386f;

    const int bj0 = blockIdx.x * TW;
    const int bi0 = blockIdx.y * TH;
    const int tid = threadIdx.y * TW + threadIdx.x;
    const int bid = blockIdx.y * NBX + blockIdx.x;

    // Build (z, q) tiles with +/-3 halo. Clamped halo cells are never indexed
    // by any clamped window of an output pixel.
    #pragma unroll
    for (int idx = tid; idx < SMH * SMW; idx += NT) {
        int lr = idx / SMW, lc = idx % SMW;
        int gr = min(max(bi0 + lr - P, 0), ROWS - 1);
        int gc = min(max(bj0 + lc - P, 0), COLS - 1);
        float d = __ldg(&depth[gr * COLS + gc]);
        float z = (d > 0.0f && d < 1.01f) ? d * 1e-3f : 0.0f;
        float cs = ((float)gc - cx) * inv_fx;
        float rs = ((float)gr - cy) * inv_fy;
        float k  = fmaf(cs, cs, fmaf(rs, rs, 1.0f));
        szZ[lr][lc] = z;
        szQ[lr][lc] = z * z * k;
    }
    __syncthreads();

    const int i = bi0 + threadIdx.y;
    const int j = bj0 + threadIdx.x;

    // Clamped window start (matches reference idif/jdif boundary shift).
    const int istart = min(max(i - P, 0), ROWS - S);
    const int jstart = min(max(j - P, 0), COLS - S);
    const int smr0 = istart - bi0 + P;   // in [0, SMH-S]
    const int smc0 = jstart - bj0 + P;   // in [0, SMW-S]

    const float z0 = szZ[threadIdx.y + P][threadIdx.x + P];
    const float q0 = szQ[threadIdx.y + P][threadIdx.x + P];
    const float x0 = z0 * (((float)j - cx) * inv_fx);
    const float y0 = z0 * (((float)i - cy) * inv_fy);

    // d^2 = q0 + qn + zn*(A_t + B_s)
    //   A_t = -2*x0*cs_{jstart+t},  B_s = -2*(y0*rs_{istart+s} + z0)
    const float m2x0 = -2.0f * x0;
    const float m2y0 = -2.0f * y0;
    float A[S];
    #pragma unroll
    for (int t = 0; t < S; t++)
        A[t] = m2x0 * (((float)(jstart + t) - cx) * inv_fx);

    float sumd0 = 0.0f, sumd1 = 0.0f;
    float sumsq = 0.0f;   // accumulates t1 = qn + zn*w; add 49*q0 at the end

    #pragma unroll
    for (int s = 0; s < S; s++) {
        const int r = smr0 + s;
        const float* rowZ = &szZ[r][smc0];
        const float* rowQ = &szQ[r][smc0];
        const float rs = ((float)(istart + s) - cy) * inv_fy;
        const float B = fmaf(m2y0, rs, -2.0f * z0);

        #pragma unroll
        for (int t = 0; t < S; t++) {
            float zn = rowZ[t];                  // LDS.32 (1 phase)
            float qn = rowQ[t];                  // LDS.32 (1 phase)
            float w  = A[t] + B;
            float t1 = fmaf(zn, w, qn);
            sumsq += t1;                         // q0 deferred
            float sq = t1 + q0;
            float dd = fsqrt_abs_approx(sq);
            if (t & 1) sumd1 += dd; else sumd0 += dd;
        }
    }

    const float sumd = sumd0 + sumd1;
    const float sumsq_t = fmaf(49.0f, q0, sumsq);

    // Unbiased variance over 49 distances.
    float var = (sumsq_t - sumd * sumd * (1.0f / 49.0f)) * (1.0f / 48.0f);
    float dev = (z0 > 0.0f) ? sqrtf(fmaxf(var, 0.0f)) : 0.0f;

    // Deterministic block reduction.
    float v = dev;
    #pragma unroll
    for (int o = 16; o; o >>= 1) v += __shfl_xor_sync(0xffffffffu, v, o);
    if ((tid & 31) == 0) wsum[tid >> 5] = v;
    __syncthreads();

    if (tid < 8) {
        float w = wsum[tid];
        #pragma unroll
        for (int o = 4; o; o >>= 1) w += __shfl_xor_sync(0x000000ffu, w, o, 8);
        if (tid == 0) {
            g_blocksums[bid] = w;
            __threadfence();
            unsigned int cnt = atomicAdd(&g_count, 1u);
            is_last = (cnt == NB - 1);
        }
    }
    __syncthreads();

    // Last finished block folds the fixed 1200-slot array (fixed order).
    if (is_last) {
        __threadfence();
        float srun = 0.0f;
        for (int idx = tid; idx < NB; idx += NT)
            srun += ((volatile float*)g_blocksums)[idx];
        #pragma unroll
        for (int o = 16; o; o >>= 1) srun += __shfl_xor_sync(0xffffffffu, srun, o);
        if ((tid & 31) == 0) wsum[tid >> 5] = srun;
        __syncthreads();
        if (tid < 8) {
            float w = wsum[tid];
            #pragma unroll
            for (int o = 4; o; o >>= 1) w += __shfl_xor_sync(0x000000ffu, w, o, 8);
            if (tid == 0) {
                out[0] = w * 100.0f;
                g_count = 0;   // re-arm for next graph replay
            }
        }
    }
}

extern "C" void kernel_launch(void* const* d_in, const int* in_sizes, int n_in,
                              void* d_out, int out_size) {
    const float* depth = (const float*)d_in[0];   // depthin (1,1,480,640)
    float* out = (float*)d_out;
    dim3 grid(NBX, NBY);
    dim3 block(TW, TH);
    stdev_fused_kernel<<<grid, block>>>(depth, out);
}